// round 1
// baseline (speedup 1.0000x reference)
#include <cuda_runtime.h>

// VisibilityHeatmap: per (b,k) keypoint, convert NDC coord -> pixel index,
// gather ONE heatmap value, threshold, broadcast mask to both coord lanes.
//
// Shapes: coords [B=32, K=64, 2] f32, heatmaps [B, K, H=256, W=256] f32.
// Output [B, K, 2] f32.
//
// Only 2048 scattered heatmap elements are ever read -> latency-bound
// micro-kernel. One thread per (b,k).

#define WIDTH 256
#define HEIGHT 256
#define THRESHOLD 0.4f

__global__ void vis_heatmap_kernel(const float* __restrict__ coords,
                                   const float* __restrict__ heatmaps,
                                   float* __restrict__ out,
                                   int n) // n = B*K
{
    int i = blockIdx.x * blockDim.x + threadIdx.x;
    if (i >= n) return;

    // Coalesced vectorized coord load: (u, v) NDC
    float2 c = reinterpret_cast<const float2*>(coords)[i];

    // ndc -> pixel, truncate toward zero (matches .astype(int32) on
    // positive-or-negative values like torch .long())
    float px = (c.x + 1.0f) * 0.5f * (float)WIDTH;
    float py = (c.y + 1.0f) * 0.5f * (float)HEIGHT;
    int u = (int)px;   // trunc toward zero
    int v = (int)py;

    bool valid = (u > -1) & (v > -1) & (v < HEIGHT) & (u < WIDTH);

    int vc = min(max(v, 0), HEIGHT - 1);
    int uc = min(max(u, 0), WIDTH - 1);

    // heatmaps[i, vc, uc] with i = b*K + k flattened over [B*K, H, W]
    float val = __ldg(&heatmaps[((size_t)i * HEIGHT + vc) * WIDTH + uc]);

    float m = (valid && (val > THRESHOLD)) ? 1.0f : 0.0f;

    // Coalesced vectorized store: broadcast mask to both lanes
    reinterpret_cast<float2*>(out)[i] = make_float2(m, m);
}

extern "C" void kernel_launch(void* const* d_in, const int* in_sizes, int n_in,
                              void* d_out, int out_size)
{
    const float* coords   = (const float*)d_in[0];
    const float* heatmaps = (const float*)d_in[1];
    float* out = (float*)d_out;

    int n = in_sizes[0] / 2;  // B*K keypoints (coords has 2 floats each)

    int threads = 256;
    int blocks = (n + threads - 1) / threads;
    vis_heatmap_kernel<<<blocks, threads>>>(coords, heatmaps, out, n);
}

// round 2
// speedup vs baseline: 1.0069x; 1.0069x over previous
#include <cuda_runtime.h>

// VisibilityHeatmap: per (b,k) keypoint, NDC coord -> pixel index, gather ONE
// heatmap value, threshold, broadcast mask to both coord lanes.
//
// coords [B=32,K=64,2] f32, heatmaps [B,K,256,256] f32, out [B,K,2] f32.
// Latency-bound micro-kernel: 2048 threads, each with a 2-deep dependent
// load chain (coord -> gather). Minimize ALU ops on that chain:
//   - unsigned range checks instead of 4 compares + clamp
//   - predicated gather (no clamp needed: invalid lanes output 0 anyway)
//   - bitfield address construction (u,v in [0,256) when valid)

#define THRESHOLD 0.4f

__global__ void __launch_bounds__(256, 1)
vis_heatmap_kernel(const float* __restrict__ coords,
                   const float* __restrict__ heatmaps,
                   float* __restrict__ out,
                   int n) // n = B*K
{
    int i = blockIdx.x * blockDim.x + threadIdx.x;
    if (i >= n) return;

    // Coalesced vectorized coord load: (u, v) NDC
    float2 c = reinterpret_cast<const float2*>(coords)[i];

    // ndc -> pixel, truncate toward zero (matches .astype(int32))
    int u = (int)((c.x + 1.0f) * 128.0f);   // 0.5 * WIDTH  = 128
    int v = (int)((c.y + 1.0f) * 128.0f);   // 0.5 * HEIGHT = 128

    // valid iff 0 <= u < 256 and 0 <= v < 256 (single unsigned compare each)
    bool valid = ((unsigned)u < 256u) & ((unsigned)v < 256u);

    // Predicated gather: when invalid, result is 0 regardless of heatmap
    // value, so skip the load entirely (no clamping needed).
    float val = 0.0f;
    if (valid) {
        // heatmaps[i][v][u] = base + ((i<<16) | (v<<8) | u)
        unsigned idx = ((unsigned)i << 16) | ((unsigned)v << 8) | (unsigned)u;
        val = __ldg(&heatmaps[idx]);
    }

    float m = (val > THRESHOLD) ? 1.0f : 0.0f;

    // Coalesced vectorized store: broadcast mask to both lanes
    reinterpret_cast<float2*>(out)[i] = make_float2(m, m);
}

extern "C" void kernel_launch(void* const* d_in, const int* in_sizes, int n_in,
                              void* d_out, int out_size)
{
    const float* coords   = (const float*)d_in[0];
    const float* heatmaps = (const float*)d_in[1];
    float* out = (float*)d_out;

    int n = in_sizes[0] / 2;  // B*K keypoints

    int threads = 256;
    int blocks = (n + threads - 1) / threads;
    vis_heatmap_kernel<<<blocks, threads>>>(coords, heatmaps, out, n);
}